// round 11
// baseline (speedup 1.0000x reference)
#include <cuda_runtime.h>
#include <cuda_fp16.h>
#include <cuda_bf16.h>
#include <cstdint>

// ---------------------------------------------------------------------------
// Problem constants
// ---------------------------------------------------------------------------
#define B_  256
#define T_  512
#define I_  300
#define H_  64
#define G3  192          // 3*H
#define NCAT 384         // 6*H
#define KP  320          // K padded (10 tiles of 32)
#define M_  (B_ * T_)    // 131072

#define BM 128
#define BN 128
#define BK 32
#define KTILES (KP / BK) // 10

// gemm smem stage layout (bytes): A1 | A2 | B1  (each 8KB)
#define STG   24576
#define OF_A1 0
#define OF_A2 8192
#define OF_B1 16384
#define GSMEM (2 * STG)

// Scratch (static device memory; no allocation allowed)
__device__ float g_xp[(size_t)M_ * NCAT];         // ~201 MB
__device__ __half g_W1[NCAT * KP];                // W fp16, [n][k] K-major, padded
__device__ float g_bcat[NCAT];
__device__ float g_feat[B_ * 256];                // [b][ hf1 | hbF | hfF | hb1 ]

// ---------------------------------------------------------------------------
// MMA / ldmatrix helpers (baseline PTX, legal on sm_103 non-'a' target)
// ---------------------------------------------------------------------------
__device__ __forceinline__ uint32_t smem_u32(const void* p) {
    uint32_t a;
    asm("{ .reg .u64 t; cvta.to.shared.u64 t, %1; cvt.u32.u64 %0, t; }"
        : "=r"(a) : "l"(p));
    return a;
}
__device__ __forceinline__ void ldsm_x4(uint32_t addr, uint32_t& r0, uint32_t& r1,
                                        uint32_t& r2, uint32_t& r3) {
    asm volatile("ldmatrix.sync.aligned.m8n8.x4.shared.b16 {%0,%1,%2,%3}, [%4];"
                 : "=r"(r0), "=r"(r1), "=r"(r2), "=r"(r3) : "r"(addr));
}
__device__ __forceinline__ void mma16816h(float* d, const uint32_t* a,
                                          uint32_t b0, uint32_t b1) {
    asm volatile(
        "mma.sync.aligned.m16n8k16.row.col.f32.f16.f16.f32 "
        "{%0,%1,%2,%3}, {%4,%5,%6,%7}, {%8,%9}, {%0,%1,%2,%3};"
        : "+f"(d[0]), "+f"(d[1]), "+f"(d[2]), "+f"(d[3])
        : "r"(a[0]), "r"(a[1]), "r"(a[2]), "r"(a[3]), "r"(b0), "r"(b1));
}

// swizzled byte offset within a [rows][32 fp16] tile (64B rows)
__device__ __forceinline__ uint32_t swz(int r, int u) {
    return (uint32_t)(r * 64 + ((u ^ ((r >> 1) & 3)) << 4));
}

// ---------------------------------------------------------------------------
// f32x2 packed helpers (for scan)
// ---------------------------------------------------------------------------
__device__ __forceinline__ unsigned long long pack2(float lo, float hi) {
    unsigned long long r;
    asm("mov.b64 %0, {%1, %2};" : "=l"(r) : "f"(lo), "f"(hi));
    return r;
}
__device__ __forceinline__ unsigned long long fma2(unsigned long long a,
                                                   unsigned long long b,
                                                   unsigned long long c) {
    unsigned long long d;
    asm("fma.rn.f32x2 %0, %1, %2, %3;" : "=l"(d) : "l"(a), "l"(b), "l"(c));
    return d;
}
__device__ __forceinline__ float2 unpack2(unsigned long long v) {
    float lo, hi;
    asm("mov.b64 {%0, %1}, %2;" : "=f"(lo), "=f"(hi) : "l"(v));
    return make_float2(lo, hi);
}
__device__ __forceinline__ float sigmoidf_(float x) {
    return __fdividef(1.f, 1.f + __expf(-x));
}
__device__ __forceinline__ float tanhf_(float x) {
    return 1.f - __fdividef(2.f, 1.f + __expf(2.f * x));
}

// ---------------------------------------------------------------------------
// Kernel D: dummy (keeps ncu capture window landing on scan; zero g_feat)
// ---------------------------------------------------------------------------
__global__ void dummy_kernel() {
    int i = blockIdx.x * blockDim.x + threadIdx.x;
    if (i < B_ * 256) g_feat[i] = 0.f;
}

// ---------------------------------------------------------------------------
// Kernel 0: build fp16 combined weight + fp32 bias
// ---------------------------------------------------------------------------
__global__ void prep_kernel(const float* __restrict__ Wif,
                            const float* __restrict__ Wib,
                            const float* __restrict__ bif,
                            const float* __restrict__ bib) {
    int i = blockIdx.x * blockDim.x + threadIdx.x;
    if (i < NCAT) g_bcat[i] = (i < G3) ? bif[i] : bib[i - G3];
    if (i < NCAT * KP) {
        int n = i / KP, k = i % KP;
        float v = 0.f;
        if (k < I_) v = (n < G3) ? Wif[n * I_ + k] : Wib[(n - G3) * I_ + k];
        g_W1[i] = __float2half_rn(v);
    }
}

// ---------------------------------------------------------------------------
// Kernel 1: HMMA fp16 2-term split GEMM — 8 warps (2M x 4N), warp tile 64x32,
//   double-buffered smem, ONE __syncthreads per K-tile. (R9 version, proven)
// ---------------------------------------------------------------------------
__global__ __launch_bounds__(256) void gemm_mma(const float* __restrict__ A) {
    extern __shared__ __align__(128) char smem[];

    const int tid = threadIdx.x;
    const int wid = tid >> 5;
    const int lid = tid & 31;
    const int m0 = blockIdx.x * BM;
    const int n0 = blockIdx.y * BN;

    const int wm = wid & 1;          // M half -> rows wm*64
    const int wn = wid >> 1;         // N quarter -> cols wn*32

    const int ar = tid >> 1;
    const int ah = (tid & 1) * 16;
    const float* Arow = A + (size_t)(m0 + ar) * I_;

    const int br = tid >> 1;
    const int bu = (tid & 1) * 2;
    const __half* B1row = g_W1 + (size_t)(n0 + br) * KP;

    float4 va[4];
    uint4 vb1[2];

    {
#pragma unroll
        for (int j = 0; j < 4; j++) {
            int c = ah + j * 4;
            va[j] = (c < I_) ? *(const float4*)(Arow + c)
                             : make_float4(0.f, 0.f, 0.f, 0.f);
        }
#pragma unroll
        for (int j = 0; j < 2; j++)
            vb1[j] = *(const uint4*)(B1row + (bu + j) * 8);
    }

    float acc[4][4][4];
#pragma unroll
    for (int i = 0; i < 4; i++)
#pragma unroll
        for (int j = 0; j < 4; j++)
#pragma unroll
            for (int q = 0; q < 4; q++) acc[i][j][q] = 0.f;

    for (int t = 0; t < KTILES; t++) {
        char* st = smem + (t & 1) * STG;
        // ---- convert + store stage t (A -> a1 + a2 fp16) ----
#pragma unroll
        for (int j = 0; j < 4; j++) {
            int col = ah + j * 4;
            uint32_t off = swz(ar, col >> 3) + (col & 7) * 2;
            float fx = va[j].x, fy = va[j].y, fz = va[j].z, fw = va[j].w;
            __half h0 = __float2half_rn(fx);
            __half h1 = __float2half_rn(fy);
            __half h2 = __float2half_rn(fz);
            __half h3 = __float2half_rn(fw);
            __half l0 = __float2half_rn(fx - __half2float(h0));
            __half l1 = __float2half_rn(fy - __half2float(h1));
            __half l2 = __float2half_rn(fz - __half2float(h2));
            __half l3 = __float2half_rn(fw - __half2float(h3));
            __half2 hp0 = __halves2half2(h0, h1), hp1 = __halves2half2(h2, h3);
            __half2 lp0 = __halves2half2(l0, l1), lp1 = __halves2half2(l2, l3);
            *(uint2*)(st + OF_A1 + off) =
                make_uint2(*(uint32_t*)&hp0, *(uint32_t*)&hp1);
            *(uint2*)(st + OF_A2 + off) =
                make_uint2(*(uint32_t*)&lp0, *(uint32_t*)&lp1);
        }
#pragma unroll
        for (int j = 0; j < 2; j++) {
            uint32_t off = swz(br, bu + j);
            *(uint4*)(st + OF_B1 + off) = vb1[j];
        }
        __syncthreads();               // the ONLY barrier per tile

        // ---- prefetch tile t+1 into regs ----
        if (t + 1 < KTILES) {
            const int k0 = (t + 1) * BK;
#pragma unroll
            for (int j = 0; j < 4; j++) {
                int c = k0 + ah + j * 4;
                va[j] = (c < I_) ? *(const float4*)(Arow + c)
                                 : make_float4(0.f, 0.f, 0.f, 0.f);
            }
#pragma unroll
            for (int j = 0; j < 2; j++)
                vb1[j] = *(const uint4*)(B1row + k0 + (bu + j) * 8);
        }

        // ---- compute stage t ----
        const uint32_t a1B = smem_u32(st + OF_A1);
        const uint32_t a2B = smem_u32(st + OF_A2);
        const uint32_t b1B = smem_u32(st + OF_B1);
#pragma unroll
        for (int s = 0; s < 2; s++) {
            uint32_t af1[4][4], af2[4][4], bf1[2][4];
            const int rA = (lid & 15);
            const int uu = s * 2 + (lid >> 4);
#pragma unroll
            for (int i = 0; i < 4; i++) {
                int r = wm * 64 + i * 16 + rA;
                uint32_t o = swz(r, uu);
                ldsm_x4(a1B + o, af1[i][0], af1[i][1], af1[i][2], af1[i][3]);
                ldsm_x4(a2B + o, af2[i][0], af2[i][1], af2[i][2], af2[i][3]);
            }
#pragma unroll
            for (int j2 = 0; j2 < 2; j2++) {
                int r = wn * 32 + j2 * 16 + rA;
                uint32_t o = swz(r, uu);
                ldsm_x4(b1B + o, bf1[j2][0], bf1[j2][1], bf1[j2][2], bf1[j2][3]);
            }
#pragma unroll
            for (int i = 0; i < 4; i++) {
#pragma unroll
                for (int j2 = 0; j2 < 2; j2++) {
#pragma unroll
                    for (int g = 0; g < 2; g++) {
                        int j = j2 * 2 + g;
                        uint32_t h0 = bf1[j2][g], h1 = bf1[j2][g + 2];
                        mma16816h(acc[i][j], af1[i], h0, h1);
                        mma16816h(acc[i][j], af2[i], h0, h1);
                    }
                }
            }
        }
    }

    const int erow = lid >> 2;
    const int ecol = (lid & 3) * 2;
#pragma unroll
    for (int i = 0; i < 4; i++) {
        int grow = m0 + wm * 64 + i * 16 + erow;
        float* out0 = g_xp + (size_t)grow * NCAT;
        float* out1 = g_xp + (size_t)(grow + 8) * NCAT;
#pragma unroll
        for (int j = 0; j < 4; j++) {
            int gcol = n0 + wn * 32 + j * 8 + ecol;
            float2 bi = *(const float2*)(g_bcat + gcol);
            *(float2*)(out0 + gcol) =
                make_float2(acc[i][j][0] + bi.x, acc[i][j][1] + bi.y);
            *(float2*)(out1 + gcol) =
                make_float2(acc[i][j][2] + bi.x, acc[i][j][3] + bi.y);
        }
    }
}

// ---------------------------------------------------------------------------
// Kernel 2: bidirectional GRU scan — thread-per-(gate,unit).
//   Grid 512 = (b,dir); block 192 threads: tid = g*64+u, g in {r,z,n}.
//   Each thread holds ONE gate row (32 f32x2 regs) and computes one 64-dot.
//   g0/g1 publish x+b+dot via smem; g2 (owner of n-gate and h[u]) applies
//   activations with its own hn/xn in registers and updates h.
//   __launch_bounds__(192,4) caps regs at 85 -> 4 blocks/SM, 24 warps/SM,
//   single wave (512 blocks <= 4*148).
// ---------------------------------------------------------------------------
__global__ __launch_bounds__(192, 4) void scan_kernel(
    const float* __restrict__ Whhf, const float* __restrict__ Whhb,
    const float* __restrict__ bhhf, const float* __restrict__ bhhb) {
    __shared__ __align__(16) float hbuf[2][H_];      // [parity][unit]
    __shared__ float sg[2][H_];                      // r,z pre-activation

    const int b = blockIdx.x >> 1;
    const int dir = blockIdx.x & 1;
    const int tid = threadIdx.x;
    const int g = tid >> 6;          // 0=r, 1=z, 2=n
    const int u = tid & 63;

    const float* Whh = dir ? Whhb : Whhf;
    const float* bhh = dir ? bhhb : bhhf;

    // my single gate row (64 floats = 32 packed pairs)
    unsigned long long w[32];
    {
        const float2* wr = (const float2*)(Whh + (size_t)tid * H_);
#pragma unroll
        for (int k = 0; k < 32; k++) {
            float2 t = wr[k];
            w[k] = pack2(t.x, t.y);
        }
    }
    const float bias = bhh[tid];

    if (tid < H_) hbuf[0][tid] = 0.f;
    float hreg = 0.f;                // live only in g==2 threads

    const int stp = dir ? -NCAT : NCAT;
    const float* p = g_xp + (size_t)b * (T_ * NCAT) +
                     (dir ? (size_t)(T_ - 1) * NCAT : 0) + dir * G3 + tid;
    float x0 = p[0];
    p += stp;
    float x1 = p[0];
    p += stp;
    __syncthreads();

    for (int s = 0; s < T_; s++) {
        // ---- my gate dot over h (2 chains of 16 fma2) ----
        const ulonglong2* hp = (const ulonglong2*)hbuf[s & 1];
        unsigned long long a0 = pack2(bias, 0.f), a1 = pack2(0.f, 0.f);
#pragma unroll
        for (int k = 0; k < 16; k++) {
            ulonglong2 hv = hp[k];                  // broadcast LDS.128
            a0 = fma2(w[2 * k], hv.x, a0);
            a1 = fma2(w[2 * k + 1], hv.y, a1);
        }
        float2 p0 = unpack2(a0), p1 = unpack2(a1);
        float dot = (p0.x + p0.y) + (p1.x + p1.y);  // includes bias

        if (g < 2) sg[g][u] = dot + x0;             // xr+hr / xz+hz

        // advance xp prefetch (all threads)
        float x0n = x1;
        if (s + 2 < T_) x1 = p[0];
        p += stp;
        __syncthreads();                            // barrier A

        if (g == 2) {
            float r = sigmoidf_(sg[0][u]);
            float z = sigmoidf_(sg[1][u]);
            float n = tanhf_(x0 + r * dot);         // dot == hn, x0 == xn
            hreg = fmaf(z, hreg - n, n);            // (1-z)*n + z*h
            hbuf[(s + 1) & 1][u] = hreg;
            if (s == 0)
                g_feat[b * 256 + (dir ? 192 : 0) + u] = hreg;
            if (s == T_ - 1)
                g_feat[b * 256 + (dir ? 64 : 128) + u] = hreg;
        }
        x0 = x0n;
        __syncthreads();                            // barrier B
    }
}

// ---------------------------------------------------------------------------
// Kernel 3: head MLP  feat[256] -> 32 (LeakyReLU) -> 1
// ---------------------------------------------------------------------------
__global__ __launch_bounds__(256) void head_kernel(
    const float* __restrict__ W1, const float* __restrict__ b1,
    const float* __restrict__ W2, const float* __restrict__ b2,
    float* __restrict__ out) {
    __shared__ float w1s[32 * 256];
    __shared__ float fs[256];
    __shared__ float hs[32];
    const int tid = threadIdx.x;
    for (int i = tid; i < 32 * 256; i += 256) w1s[i] = W1[i];
    const int j = tid >> 3, p = tid & 7;
    const float b1j = b1[j];
    const float w2j = W2[j];
    __syncthreads();

    for (int bb = 0; bb < 8; bb++) {
        const int b = blockIdx.x * 8 + bb;
        fs[tid] = g_feat[b * 256 + tid];
        __syncthreads();

        const float* w = w1s + j * 256 + p * 32;
        const float* f = fs + p * 32;
        float acc = 0.f;
#pragma unroll
        for (int i = 0; i < 32; i++) acc = fmaf(f[i], w[i], acc);
        acc += __shfl_xor_sync(0xffffffffu, acc, 1);
        acc += __shfl_xor_sync(0xffffffffu, acc, 2);
        acc += __shfl_xor_sync(0xffffffffu, acc, 4);
        if (p == 0) {
            float hv = acc + b1j;
            hv = (hv >= 0.f) ? hv : 0.01f * hv;
            hs[j] = hv * w2j;
        }
        __syncthreads();
        if (tid < 32) {
            float v = hs[tid];
#pragma unroll
            for (int o = 16; o > 0; o >>= 1) v += __shfl_xor_sync(0xffffffffu, v, o);
            if (tid == 0) out[b] = v + b2[0];
        }
        __syncthreads();
    }
}

// ---------------------------------------------------------------------------
extern "C" void kernel_launch(void* const* d_in, const int* in_sizes, int n_in,
                              void* d_out, int out_size) {
    const float* x    = (const float*)d_in[0];
    const float* Wif  = (const float*)d_in[1];
    const float* Whhf = (const float*)d_in[2];
    const float* bif  = (const float*)d_in[3];
    const float* bhhf = (const float*)d_in[4];
    const float* Wib  = (const float*)d_in[5];
    const float* Whhb = (const float*)d_in[6];
    const float* bib  = (const float*)d_in[7];
    const float* bhhb = (const float*)d_in[8];
    const float* W1   = (const float*)d_in[9];
    const float* b1   = (const float*)d_in[10];
    const float* W2   = (const float*)d_in[11];
    const float* b2   = (const float*)d_in[12];
    float* out = (float*)d_out;

    cudaFuncSetAttribute(gemm_mma, cudaFuncAttributeMaxDynamicSharedMemorySize,
                         GSMEM);

    dummy_kernel<<<B_, 256>>>();

    prep_kernel<<<(NCAT * KP + 255) / 256, 256>>>(Wif, Wib, bif, bib);

    dim3 ggrid(M_ / BM, NCAT / BN);
    gemm_mma<<<ggrid, 256, GSMEM>>>(x);

    scan_kernel<<<2 * B_, 192>>>(Whhf, Whhb, bhhf, bhhb);

    head_kernel<<<B_ / 8, 256>>>(W1, b1, W2, b2, out);
}

// round 12
// speedup vs baseline: 1.0540x; 1.0540x over previous
#include <cuda_runtime.h>
#include <cuda_fp16.h>
#include <cuda_bf16.h>
#include <cstdint>

// ---------------------------------------------------------------------------
// Problem constants
// ---------------------------------------------------------------------------
#define B_  256
#define T_  512
#define I_  300
#define H_  64
#define G3  192          // 3*H
#define NCAT 384         // 6*H
#define KP  320          // K padded (5 tiles of 64)
#define M_  (B_ * T_)    // 131072

#define BM 128
#define BN 128
#define BK 64
#define KTILES (KP / BK) // 5

// gemm smem stage layout (bytes): A1 | A2 | B1  (each 16KB, 128B rows)
#define STG   49152
#define OF_A1 0
#define OF_A2 16384
#define OF_B1 32768
#define GSMEM (2 * STG)

// Scratch (static device memory; no allocation allowed)
__device__ float g_xp[(size_t)M_ * NCAT];         // ~201 MB
__device__ __half g_W1[NCAT * KP];                // W fp16, [n][k] K-major, padded
__device__ float g_bcat[NCAT];
__device__ float g_feat[B_ * 256];                // [b][ hf1 | hbF | hfF | hb1 ]

// ---------------------------------------------------------------------------
// MMA / ldmatrix / cp.async helpers (baseline PTX, legal on sm_103)
// ---------------------------------------------------------------------------
__device__ __forceinline__ uint32_t smem_u32(const void* p) {
    uint32_t a;
    asm("{ .reg .u64 t; cvta.to.shared.u64 t, %1; cvt.u32.u64 %0, t; }"
        : "=r"(a) : "l"(p));
    return a;
}
__device__ __forceinline__ void ldsm_x4(uint32_t addr, uint32_t& r0, uint32_t& r1,
                                        uint32_t& r2, uint32_t& r3) {
    asm volatile("ldmatrix.sync.aligned.m8n8.x4.shared.b16 {%0,%1,%2,%3}, [%4];"
                 : "=r"(r0), "=r"(r1), "=r"(r2), "=r"(r3) : "r"(addr));
}
__device__ __forceinline__ void mma16816h(float* d, const uint32_t* a,
                                          uint32_t b0, uint32_t b1) {
    asm volatile(
        "mma.sync.aligned.m16n8k16.row.col.f32.f16.f16.f32 "
        "{%0,%1,%2,%3}, {%4,%5,%6,%7}, {%8,%9}, {%0,%1,%2,%3};"
        : "+f"(d[0]), "+f"(d[1]), "+f"(d[2]), "+f"(d[3])
        : "r"(a[0]), "r"(a[1]), "r"(a[2]), "r"(a[3]), "r"(b0), "r"(b1));
}
__device__ __forceinline__ void cp_async16(uint32_t dst, const void* src) {
    asm volatile("cp.async.cg.shared.global [%0], [%1], 16;"
                 :: "r"(dst), "l"(src) : "memory");
}
__device__ __forceinline__ void cp_commit() {
    asm volatile("cp.async.commit_group;" ::: "memory");
}
__device__ __forceinline__ void cp_wait0() {
    asm volatile("cp.async.wait_group 0;" ::: "memory");
}

// swizzled byte offset within a [rows][64 fp16] tile (128B rows, SW128-style)
__device__ __forceinline__ uint32_t swzB(int r, int u) {
    return (uint32_t)(r * 128 + ((u ^ (r & 7)) << 4));
}

// ---------------------------------------------------------------------------
// f32x2 packed helpers (for scan)
// ---------------------------------------------------------------------------
__device__ __forceinline__ unsigned long long pack2(float lo, float hi) {
    unsigned long long r;
    asm("mov.b64 %0, {%1, %2};" : "=l"(r) : "f"(lo), "f"(hi));
    return r;
}
__device__ __forceinline__ unsigned long long fma2(unsigned long long a,
                                                   unsigned long long b,
                                                   unsigned long long c) {
    unsigned long long d;
    asm("fma.rn.f32x2 %0, %1, %2, %3;" : "=l"(d) : "l"(a), "l"(b), "l"(c));
    return d;
}
__device__ __forceinline__ float2 unpack2(unsigned long long v) {
    float lo, hi;
    asm("mov.b64 {%0, %1}, %2;" : "=f"(lo), "=f"(hi) : "l"(v));
    return make_float2(lo, hi);
}
__device__ __forceinline__ float sigmoidf_(float x) {
    return __fdividef(1.f, 1.f + __expf(-x));
}
__device__ __forceinline__ float tanhf_(float x) {
    return 1.f - __fdividef(2.f, 1.f + __expf(2.f * x));
}

// ---------------------------------------------------------------------------
// Kernel 0: build fp16 combined weight + fp32 bias
// ---------------------------------------------------------------------------
__global__ void prep_kernel(const float* __restrict__ Wif,
                            const float* __restrict__ Wib,
                            const float* __restrict__ bif,
                            const float* __restrict__ bib) {
    int i = blockIdx.x * blockDim.x + threadIdx.x;
    if (i < NCAT) g_bcat[i] = (i < G3) ? bif[i] : bib[i - G3];
    if (i < NCAT * KP) {
        int n = i / KP, k = i % KP;
        float v = 0.f;
        if (k < I_) v = (n < G3) ? Wif[n * I_ + k] : Wib[(n - G3) * I_ + k];
        g_W1[i] = __float2half_rn(v);
    }
}

// ---------------------------------------------------------------------------
// Kernel 1: HMMA fp16 2-term split GEMM — BK=64, 5 K-tiles, cp.async B,
//   double-buffered smem, ONE __syncthreads per K-tile.
//   8 warps (2M x 4N), warp tile 64x32.
//   xp = (a1 + a2) @ B1^T + bias,  a1 = fp16(x), a2 = fp16(x - a1)
// ---------------------------------------------------------------------------
__global__ __launch_bounds__(256) void gemm_mma(const float* __restrict__ A) {
    extern __shared__ __align__(128) char smem[];

    const int tid = threadIdx.x;
    const int wid = tid >> 5;
    const int lid = tid & 31;
    const int m0 = blockIdx.x * BM;
    const int n0 = blockIdx.y * BN;

    const int wm = wid & 1;          // M half -> rows wm*64
    const int wn = wid >> 1;         // N quarter -> cols wn*32

    // A mapping: row = tid>>1 (0..127), cols colbase..colbase+31
    const int ar = tid >> 1;
    const int acb = (tid & 1) * 32;
    const float* Arow = A + (size_t)(m0 + ar) * I_;

    // B mapping: row = tid>>1, four 16B chunks u = (tid&1)*4 + j
    const int br = tid >> 1;
    const int bu = (tid & 1) * 4;
    const __half* B1row = g_W1 + (size_t)(n0 + br) * KP;

    float4 va[8];

    // ---- preload stage 0 ----
    {
        char* st = smem;
#pragma unroll
        for (int j = 0; j < 4; j++)
            cp_async16(smem_u32(st + OF_B1) + swzB(br, bu + j),
                       B1row + (bu + j) * 8);
        cp_commit();
#pragma unroll
        for (int j = 0; j < 8; j++) {
            int c = acb + j * 4;
            va[j] = (c < I_) ? *(const float4*)(Arow + c)
                             : make_float4(0.f, 0.f, 0.f, 0.f);
        }
    }

    float acc[4][4][4];
#pragma unroll
    for (int i = 0; i < 4; i++)
#pragma unroll
        for (int j = 0; j < 4; j++)
#pragma unroll
            for (int q = 0; q < 4; q++) acc[i][j][q] = 0.f;

    for (int t = 0; t < KTILES; t++) {
        char* st = smem + (t & 1) * STG;
        // ---- convert + store A stage t (a1/a2 fp16, 4x STS.128 each) ----
#pragma unroll
        for (int m = 0; m < 4; m++) {
            // 8 floats from va[2m], va[2m+1] -> one 16B chunk u = (acb>>3)+m
            float f[8] = {va[2 * m].x, va[2 * m].y, va[2 * m].z, va[2 * m].w,
                          va[2 * m + 1].x, va[2 * m + 1].y, va[2 * m + 1].z,
                          va[2 * m + 1].w};
            uint32_t hp[4], lp[4];
#pragma unroll
            for (int q = 0; q < 4; q++) {
                __half h0 = __float2half_rn(f[2 * q]);
                __half h1 = __float2half_rn(f[2 * q + 1]);
                __half l0 = __float2half_rn(f[2 * q] - __half2float(h0));
                __half l1 = __float2half_rn(f[2 * q + 1] - __half2float(h1));
                __half2 hh = __halves2half2(h0, h1), ll = __halves2half2(l0, l1);
                hp[q] = *(uint32_t*)&hh;
                lp[q] = *(uint32_t*)&ll;
            }
            uint32_t off = swzB(ar, (acb >> 3) + m);
            *(uint4*)(st + OF_A1 + off) = make_uint4(hp[0], hp[1], hp[2], hp[3]);
            *(uint4*)(st + OF_A2 + off) = make_uint4(lp[0], lp[1], lp[2], lp[3]);
        }

        cp_wait0();                    // B stage t landed
        __syncthreads();               // the ONLY barrier per tile

        // ---- kick off stage t+1 (B via cp.async, A via registers) ----
        if (t + 1 < KTILES) {
            char* sn = smem + ((t + 1) & 1) * STG;
            const int k0 = (t + 1) * BK;
#pragma unroll
            for (int j = 0; j < 4; j++)
                cp_async16(smem_u32(sn + OF_B1) + swzB(br, bu + j),
                           B1row + k0 + (bu + j) * 8);
            cp_commit();
#pragma unroll
            for (int j = 0; j < 8; j++) {
                int c = k0 + acb + j * 4;
                va[j] = (c < I_) ? *(const float4*)(Arow + c)
                                 : make_float4(0.f, 0.f, 0.f, 0.f);
            }
        }

        // ---- compute stage t: 4 k16 steps ----
        const uint32_t a1B = smem_u32(st + OF_A1);
        const uint32_t a2B = smem_u32(st + OF_A2);
        const uint32_t b1B = smem_u32(st + OF_B1);
#pragma unroll
        for (int s = 0; s < 4; s++) {
            uint32_t af1[4][4], af2[4][4], bf1[2][4];
            const int rA = (lid & 15);
            const int uu = s * 2 + (lid >> 4);
#pragma unroll
            for (int i = 0; i < 4; i++) {
                int r = wm * 64 + i * 16 + rA;
                uint32_t o = swzB(r, uu);
                ldsm_x4(a1B + o, af1[i][0], af1[i][1], af1[i][2], af1[i][3]);
                ldsm_x4(a2B + o, af2[i][0], af2[i][1], af2[i][2], af2[i][3]);
            }
#pragma unroll
            for (int j2 = 0; j2 < 2; j2++) {
                int r = wn * 32 + j2 * 16 + rA;
                uint32_t o = swzB(r, uu);
                ldsm_x4(b1B + o, bf1[j2][0], bf1[j2][1], bf1[j2][2], bf1[j2][3]);
            }
#pragma unroll
            for (int i = 0; i < 4; i++) {
#pragma unroll
                for (int j2 = 0; j2 < 2; j2++) {
#pragma unroll
                    for (int g = 0; g < 2; g++) {
                        int j = j2 * 2 + g;
                        uint32_t h0 = bf1[j2][g], h1 = bf1[j2][g + 2];
                        mma16816h(acc[i][j], af1[i], h0, h1);
                        mma16816h(acc[i][j], af2[i], h0, h1);
                    }
                }
            }
        }
    }

    const int erow = lid >> 2;
    const int ecol = (lid & 3) * 2;
#pragma unroll
    for (int i = 0; i < 4; i++) {
        int grow = m0 + wm * 64 + i * 16 + erow;
        float* out0 = g_xp + (size_t)grow * NCAT;
        float* out1 = g_xp + (size_t)(grow + 8) * NCAT;
#pragma unroll
        for (int j = 0; j < 4; j++) {
            int gcol = n0 + wn * 32 + j * 8 + ecol;
            float2 bi = *(const float2*)(g_bcat + gcol);
            *(float2*)(out0 + gcol) =
                make_float2(acc[i][j][0] + bi.x, acc[i][j][1] + bi.y);
            *(float2*)(out1 + gcol) =
                make_float2(acc[i][j][2] + bi.x, acc[i][j][3] + bi.y);
        }
    }
}

// ---------------------------------------------------------------------------
// Kernel 2: bidirectional GRU scan — R8-exact (measured best: 331us).
//   Grid 512 = (b, dir); block 64 threads, thread owns unit u with all three
//   W_hh rows in registers; ping-pong h in smem; ONE barrier per step.
// ---------------------------------------------------------------------------
__global__ __launch_bounds__(64) void scan_kernel(
    const float* __restrict__ Whhf, const float* __restrict__ Whhb,
    const float* __restrict__ bhhf, const float* __restrict__ bhhb) {
    __shared__ __align__(16) float hbuf[2][H_];      // [parity][unit]

    const int b = blockIdx.x >> 1;
    const int dir = blockIdx.x & 1;
    const int u = threadIdx.x;

    const float* Whh = dir ? Whhb : Whhf;
    const float* bhh = dir ? bhhb : bhhf;

    unsigned long long wr[32], wz[32], wn_[32];
    {
        const float2* r0 = (const float2*)(Whh + (size_t)u * H_);
        const float2* r1 = (const float2*)(Whh + (size_t)(64 + u) * H_);
        const float2* r2 = (const float2*)(Whh + (size_t)(128 + u) * H_);
#pragma unroll
        for (int k = 0; k < 32; k++) {
            float2 a = r0[k], c = r1[k], d = r2[k];
            wr[k] = pack2(a.x, a.y);
            wz[k] = pack2(c.x, c.y);
            wn_[k] = pack2(d.x, d.y);
        }
    }
    const float br_ = bhh[u];
    const float bz_ = bhh[64 + u];
    const float bn_ = bhh[128 + u];

    hbuf[0][u] = 0.f;
    float hreg = 0.f;

    const int stp = dir ? -NCAT : NCAT;
    const float* p = g_xp + (size_t)b * (T_ * NCAT) +
                     (dir ? (size_t)(T_ - 1) * NCAT : 0) + dir * G3 + u;
    float xr0 = p[0], xz0 = p[64], xn0 = p[128];
    p += stp;
    float xr1 = p[0], xz1 = p[64], xn1 = p[128];
    p += stp;
    __syncthreads();

    for (int s = 0; s < T_; s++) {
        const ulonglong2* hp = (const ulonglong2*)hbuf[s & 1];
        unsigned long long ar0 = pack2(br_, 0.f), ar1 = pack2(0.f, 0.f);
        unsigned long long az0 = pack2(bz_, 0.f), az1 = pack2(0.f, 0.f);
        unsigned long long an0 = pack2(bn_, 0.f), an1 = pack2(0.f, 0.f);
#pragma unroll
        for (int k = 0; k < 16; k++) {
            ulonglong2 hv = hp[k];                  // broadcast LDS.128
            ar0 = fma2(wr[2 * k], hv.x, ar0);
            ar1 = fma2(wr[2 * k + 1], hv.y, ar1);
            az0 = fma2(wz[2 * k], hv.x, az0);
            az1 = fma2(wz[2 * k + 1], hv.y, az1);
            an0 = fma2(wn_[2 * k], hv.x, an0);
            an1 = fma2(wn_[2 * k + 1], hv.y, an1);
        }
        float2 pr0 = unpack2(ar0), pr1 = unpack2(ar1);
        float2 pz0 = unpack2(az0), pz1 = unpack2(az1);
        float2 pn0 = unpack2(an0), pn1 = unpack2(an1);
        float hr = (pr0.x + pr0.y) + (pr1.x + pr1.y);
        float hz = (pz0.x + pz0.y) + (pz1.x + pz1.y);
        float hn = (pn0.x + pn0.y) + (pn1.x + pn1.y);

        float r = sigmoidf_(xr0 + hr);
        float z = sigmoidf_(xz0 + hz);
        float n = tanhf_(xn0 + r * hn);
        hreg = fmaf(z, hreg - n, n);                // (1-z)*n + z*h
        hbuf[(s + 1) & 1][u] = hreg;

        if (s == 0)
            g_feat[b * 256 + (dir ? 192 : 0) + u] = hreg;
        if (s == T_ - 1)
            g_feat[b * 256 + (dir ? 64 : 128) + u] = hreg;

        xr0 = xr1; xz0 = xz1; xn0 = xn1;
        if (s + 2 < T_) {
            xr1 = p[0]; xz1 = p[64]; xn1 = p[128];
        }
        p += stp;
        __syncthreads();
    }
}

// ---------------------------------------------------------------------------
// Kernel 3: head MLP  feat[256] -> 32 (LeakyReLU) -> 1
// ---------------------------------------------------------------------------
__global__ __launch_bounds__(256) void head_kernel(
    const float* __restrict__ W1, const float* __restrict__ b1,
    const float* __restrict__ W2, const float* __restrict__ b2,
    float* __restrict__ out) {
    __shared__ float w1s[32 * 256];
    __shared__ float fs[256];
    __shared__ float hs[32];
    const int tid = threadIdx.x;
    for (int i = tid; i < 32 * 256; i += 256) w1s[i] = W1[i];
    const int j = tid >> 3, p = tid & 7;
    const float b1j = b1[j];
    const float w2j = W2[j];
    __syncthreads();

    for (int bb = 0; bb < 8; bb++) {
        const int b = blockIdx.x * 8 + bb;
        fs[tid] = g_feat[b * 256 + tid];
        __syncthreads();

        const float* w = w1s + j * 256 + p * 32;
        const float* f = fs + p * 32;
        float acc = 0.f;
#pragma unroll
        for (int i = 0; i < 32; i++) acc = fmaf(f[i], w[i], acc);
        acc += __shfl_xor_sync(0xffffffffu, acc, 1);
        acc += __shfl_xor_sync(0xffffffffu, acc, 2);
        acc += __shfl_xor_sync(0xffffffffu, acc, 4);
        if (p == 0) {
            float hv = acc + b1j;
            hv = (hv >= 0.f) ? hv : 0.01f * hv;
            hs[j] = hv * w2j;
        }
        __syncthreads();
        if (tid < 32) {
            float v = hs[tid];
#pragma unroll
            for (int o = 16; o > 0; o >>= 1) v += __shfl_xor_sync(0xffffffffu, v, o);
            if (tid == 0) out[b] = v + b2[0];
        }
        __syncthreads();
    }
}

// ---------------------------------------------------------------------------
extern "C" void kernel_launch(void* const* d_in, const int* in_sizes, int n_in,
                              void* d_out, int out_size) {
    const float* x    = (const float*)d_in[0];
    const float* Wif  = (const float*)d_in[1];
    const float* Whhf = (const float*)d_in[2];
    const float* bif  = (const float*)d_in[3];
    const float* bhhf = (const float*)d_in[4];
    const float* Wib  = (const float*)d_in[5];
    const float* Whhb = (const float*)d_in[6];
    const float* bib  = (const float*)d_in[7];
    const float* bhhb = (const float*)d_in[8];
    const float* W1   = (const float*)d_in[9];
    const float* b1   = (const float*)d_in[10];
    const float* W2   = (const float*)d_in[11];
    const float* b2   = (const float*)d_in[12];
    float* out = (float*)d_out;

    cudaFuncSetAttribute(gemm_mma, cudaFuncAttributeMaxDynamicSharedMemorySize,
                         GSMEM);

    prep_kernel<<<(NCAT * KP + 255) / 256, 256>>>(Wif, Wib, bif, bib);

    dim3 ggrid(M_ / BM, NCAT / BN);
    gemm_mma<<<ggrid, 256, GSMEM>>>(x);

    scan_kernel<<<2 * B_, 64>>>(Whhf, Whhb, bhhf, bhhb);

    head_kernel<<<B_ / 8, 256>>>(W1, b1, W2, b2, out);
}

// round 13
// speedup vs baseline: 1.1766x; 1.1164x over previous
#include <cuda_runtime.h>
#include <cuda_fp16.h>
#include <cuda_bf16.h>
#include <cstdint>

// ---------------------------------------------------------------------------
// Problem constants
// ---------------------------------------------------------------------------
#define B_  256
#define T_  512
#define I_  300
#define H_  64
#define G3  192          // 3*H
#define NCAT 384         // 6*H
#define KP  320          // K padded (5 tiles of 64)
#define M_  (B_ * T_)    // 131072

#define BM 128
#define BN 128
#define BK 64
#define KTILES (KP / BK) // 5

// gemm smem stage layout (bytes): A1 | B1  (each 16KB, 128B rows)
#define STG   32768
#define OF_A1 0
#define OF_B1 16384
#define GSMEM (2 * STG)

// Scratch (static device memory; no allocation allowed)
__device__ float g_xp[(size_t)M_ * NCAT];         // ~201 MB
__device__ __half g_W1[NCAT * KP];                // W fp16, [n][k] K-major, padded
__device__ float g_bcat[NCAT];
__device__ float g_feat[B_ * 256];                // [b][ hf1 | hbF | hfF | hb1 ]

// ---------------------------------------------------------------------------
// MMA / ldmatrix / cp.async helpers (baseline PTX, legal on sm_103)
// ---------------------------------------------------------------------------
__device__ __forceinline__ uint32_t smem_u32(const void* p) {
    uint32_t a;
    asm("{ .reg .u64 t; cvta.to.shared.u64 t, %1; cvt.u32.u64 %0, t; }"
        : "=r"(a) : "l"(p));
    return a;
}
__device__ __forceinline__ void ldsm_x4(uint32_t addr, uint32_t& r0, uint32_t& r1,
                                        uint32_t& r2, uint32_t& r3) {
    asm volatile("ldmatrix.sync.aligned.m8n8.x4.shared.b16 {%0,%1,%2,%3}, [%4];"
                 : "=r"(r0), "=r"(r1), "=r"(r2), "=r"(r3) : "r"(addr));
}
__device__ __forceinline__ void mma16816h(float* d, const uint32_t* a,
                                          uint32_t b0, uint32_t b1) {
    asm volatile(
        "mma.sync.aligned.m16n8k16.row.col.f32.f16.f16.f32 "
        "{%0,%1,%2,%3}, {%4,%5,%6,%7}, {%8,%9}, {%0,%1,%2,%3};"
        : "+f"(d[0]), "+f"(d[1]), "+f"(d[2]), "+f"(d[3])
        : "r"(a[0]), "r"(a[1]), "r"(a[2]), "r"(a[3]), "r"(b0), "r"(b1));
}
__device__ __forceinline__ void cp_async16(uint32_t dst, const void* src) {
    asm volatile("cp.async.cg.shared.global [%0], [%1], 16;"
                 :: "r"(dst), "l"(src) : "memory");
}
__device__ __forceinline__ void cp_commit() {
    asm volatile("cp.async.commit_group;" ::: "memory");
}
__device__ __forceinline__ void cp_wait0() {
    asm volatile("cp.async.wait_group 0;" ::: "memory");
}

// swizzled byte offset within a [rows][64 fp16] tile (128B rows, SW128-style)
__device__ __forceinline__ uint32_t swzB(int r, int u) {
    return (uint32_t)(r * 128 + ((u ^ (r & 7)) << 4));
}

// ---------------------------------------------------------------------------
// f32x2 packed helpers (for scan)
// ---------------------------------------------------------------------------
__device__ __forceinline__ unsigned long long pack2(float lo, float hi) {
    unsigned long long r;
    asm("mov.b64 %0, {%1, %2};" : "=l"(r) : "f"(lo), "f"(hi));
    return r;
}
__device__ __forceinline__ unsigned long long fma2(unsigned long long a,
                                                   unsigned long long b,
                                                   unsigned long long c) {
    unsigned long long d;
    asm("fma.rn.f32x2 %0, %1, %2, %3;" : "=l"(d) : "l"(a), "l"(b), "l"(c));
    return d;
}
__device__ __forceinline__ float2 unpack2(unsigned long long v) {
    float lo, hi;
    asm("mov.b64 {%0, %1}, %2;" : "=f"(lo), "=f"(hi) : "l"(v));
    return make_float2(lo, hi);
}
__device__ __forceinline__ float sigmoidf_(float x) {
    return __fdividef(1.f, 1.f + __expf(-x));
}
__device__ __forceinline__ float tanhf_(float x) {
    return 1.f - __fdividef(2.f, 1.f + __expf(2.f * x));
}

// ---------------------------------------------------------------------------
// Dummy kernels: shift the profiler's 4th-launch capture onto gemm_mma
// ---------------------------------------------------------------------------
__global__ void dummyA_kernel() {}
__global__ void dummyB_kernel() {}

// ---------------------------------------------------------------------------
// Kernel 0: build fp16 combined weight + fp32 bias
// ---------------------------------------------------------------------------
__global__ void prep_kernel(const float* __restrict__ Wif,
                            const float* __restrict__ Wib,
                            const float* __restrict__ bif,
                            const float* __restrict__ bib) {
    int i = blockIdx.x * blockDim.x + threadIdx.x;
    if (i < NCAT) g_bcat[i] = (i < G3) ? bif[i] : bib[i - G3];
    if (i < NCAT * KP) {
        int n = i / KP, k = i % KP;
        float v = 0.f;
        if (k < I_) v = (n < G3) ? Wif[n * I_ + k] : Wib[(n - G3) * I_ + k];
        g_W1[i] = __float2half_rn(v);
    }
}

// ---------------------------------------------------------------------------
// Kernel 1: HMMA fp16 single-pass GEMM — BK=64, 5 K-tiles, cp.async B,
//   double-buffered smem, ONE __syncthreads per K-tile.
//   8 warps (2M x 4N), warp tile 64x32.
//   xp = fp16(x) @ fp16(W)^T + bias   (fp32 accumulate)
// ---------------------------------------------------------------------------
__global__ __launch_bounds__(256) void gemm_mma(const float* __restrict__ A) {
    extern __shared__ __align__(128) char smem[];

    const int tid = threadIdx.x;
    const int wid = tid >> 5;
    const int lid = tid & 31;
    const int m0 = blockIdx.x * BM;
    const int n0 = blockIdx.y * BN;

    const int wm = wid & 1;          // M half -> rows wm*64
    const int wn = wid >> 1;         // N quarter -> cols wn*32

    // A mapping: row = tid>>1 (0..127), cols colbase..colbase+31
    const int ar = tid >> 1;
    const int acb = (tid & 1) * 32;
    const float* Arow = A + (size_t)(m0 + ar) * I_;

    // B mapping: row = tid>>1, four 16B chunks u = (tid&1)*4 + j
    const int br = tid >> 1;
    const int bu = (tid & 1) * 4;
    const __half* B1row = g_W1 + (size_t)(n0 + br) * KP;

    float4 va[8];

    // ---- preload stage 0 ----
    {
        char* st = smem;
#pragma unroll
        for (int j = 0; j < 4; j++)
            cp_async16(smem_u32(st + OF_B1) + swzB(br, bu + j),
                       B1row + (bu + j) * 8);
        cp_commit();
#pragma unroll
        for (int j = 0; j < 8; j++) {
            int c = acb + j * 4;
            va[j] = (c < I_) ? *(const float4*)(Arow + c)
                             : make_float4(0.f, 0.f, 0.f, 0.f);
        }
    }

    float acc[4][4][4];
#pragma unroll
    for (int i = 0; i < 4; i++)
#pragma unroll
        for (int j = 0; j < 4; j++)
#pragma unroll
            for (int q = 0; q < 4; q++) acc[i][j][q] = 0.f;

    for (int t = 0; t < KTILES; t++) {
        char* st = smem + (t & 1) * STG;
        // ---- convert + store A stage t (fp16, 4x STS.128) ----
#pragma unroll
        for (int m = 0; m < 4; m++) {
            float f[8] = {va[2 * m].x, va[2 * m].y, va[2 * m].z, va[2 * m].w,
                          va[2 * m + 1].x, va[2 * m + 1].y, va[2 * m + 1].z,
                          va[2 * m + 1].w};
            uint32_t hp[4];
#pragma unroll
            for (int q = 0; q < 4; q++) {
                __half2 hh = __halves2half2(__float2half_rn(f[2 * q]),
                                            __float2half_rn(f[2 * q + 1]));
                hp[q] = *(uint32_t*)&hh;
            }
            uint32_t off = swzB(ar, (acb >> 3) + m);
            *(uint4*)(st + OF_A1 + off) = make_uint4(hp[0], hp[1], hp[2], hp[3]);
        }

        cp_wait0();                    // B stage t landed
        __syncthreads();               // the ONLY barrier per tile

        // ---- kick off stage t+1 (B via cp.async, A via registers) ----
        if (t + 1 < KTILES) {
            char* sn = smem + ((t + 1) & 1) * STG;
            const int k0 = (t + 1) * BK;
#pragma unroll
            for (int j = 0; j < 4; j++)
                cp_async16(smem_u32(sn + OF_B1) + swzB(br, bu + j),
                           B1row + k0 + (bu + j) * 8);
            cp_commit();
#pragma unroll
            for (int j = 0; j < 8; j++) {
                int c = k0 + acb + j * 4;
                va[j] = (c < I_) ? *(const float4*)(Arow + c)
                                 : make_float4(0.f, 0.f, 0.f, 0.f);
            }
        }

        // ---- compute stage t: 4 k16 steps ----
        const uint32_t a1B = smem_u32(st + OF_A1);
        const uint32_t b1B = smem_u32(st + OF_B1);
#pragma unroll
        for (int s = 0; s < 4; s++) {
            uint32_t af1[4][4], bf1[2][4];
            const int rA = (lid & 15);
            const int uu = s * 2 + (lid >> 4);
#pragma unroll
            for (int i = 0; i < 4; i++) {
                int r = wm * 64 + i * 16 + rA;
                uint32_t o = swzB(r, uu);
                ldsm_x4(a1B + o, af1[i][0], af1[i][1], af1[i][2], af1[i][3]);
            }
#pragma unroll
            for (int j2 = 0; j2 < 2; j2++) {
                int r = wn * 32 + j2 * 16 + rA;
                uint32_t o = swzB(r, uu);
                ldsm_x4(b1B + o, bf1[j2][0], bf1[j2][1], bf1[j2][2], bf1[j2][3]);
            }
#pragma unroll
            for (int i = 0; i < 4; i++) {
#pragma unroll
                for (int j2 = 0; j2 < 2; j2++) {
#pragma unroll
                    for (int g = 0; g < 2; g++) {
                        int j = j2 * 2 + g;
                        mma16816h(acc[i][j], af1[i], bf1[j2][g], bf1[j2][g + 2]);
                    }
                }
            }
        }
    }

    const int erow = lid >> 2;
    const int ecol = (lid & 3) * 2;
#pragma unroll
    for (int i = 0; i < 4; i++) {
        int grow = m0 + wm * 64 + i * 16 + erow;
        float* out0 = g_xp + (size_t)grow * NCAT;
        float* out1 = g_xp + (size_t)(grow + 8) * NCAT;
#pragma unroll
        for (int j = 0; j < 4; j++) {
            int gcol = n0 + wn * 32 + j * 8 + ecol;
            float2 bi = *(const float2*)(g_bcat + gcol);
            *(float2*)(out0 + gcol) =
                make_float2(acc[i][j][0] + bi.x, acc[i][j][1] + bi.y);
            *(float2*)(out1 + gcol) =
                make_float2(acc[i][j][2] + bi.x, acc[i][j][3] + bi.y);
        }
    }
}

// ---------------------------------------------------------------------------
// Kernel 2: bidirectional GRU scan — R8-exact (measured best: 331us).
//   Grid 512 = (b, dir); block 64 threads, thread owns unit u with all three
//   W_hh rows in registers; ping-pong h in smem; ONE barrier per step.
// ---------------------------------------------------------------------------
__global__ __launch_bounds__(64) void scan_kernel(
    const float* __restrict__ Whhf, const float* __restrict__ Whhb,
    const float* __restrict__ bhhf, const float* __restrict__ bhhb) {
    __shared__ __align__(16) float hbuf[2][H_];      // [parity][unit]

    const int b = blockIdx.x >> 1;
    const int dir = blockIdx.x & 1;
    const int u = threadIdx.x;

    const float* Whh = dir ? Whhb : Whhf;
    const float* bhh = dir ? bhhb : bhhf;

    unsigned long long wr[32], wz[32], wn_[32];
    {
        const float2* r0 = (const float2*)(Whh + (size_t)u * H_);
        const float2* r1 = (const float2*)(Whh + (size_t)(64 + u) * H_);
        const float2* r2 = (const float2*)(Whh + (size_t)(128 + u) * H_);
#pragma unroll
        for (int k = 0; k < 32; k++) {
            float2 a = r0[k], c = r1[k], d = r2[k];
            wr[k] = pack2(a.x, a.y);
            wz[k] = pack2(c.x, c.y);
            wn_[k] = pack2(d.x, d.y);
        }
    }
    const float br_ = bhh[u];
    const float bz_ = bhh[64 + u];
    const float bn_ = bhh[128 + u];

    hbuf[0][u] = 0.f;
    float hreg = 0.f;

    const int stp = dir ? -NCAT : NCAT;
    const float* p = g_xp + (size_t)b * (T_ * NCAT) +
                     (dir ? (size_t)(T_ - 1) * NCAT : 0) + dir * G3 + u;
    float xr0 = p[0], xz0 = p[64], xn0 = p[128];
    p += stp;
    float xr1 = p[0], xz1 = p[64], xn1 = p[128];
    p += stp;
    __syncthreads();

    for (int s = 0; s < T_; s++) {
        const ulonglong2* hp = (const ulonglong2*)hbuf[s & 1];
        unsigned long long ar0 = pack2(br_, 0.f), ar1 = pack2(0.f, 0.f);
        unsigned long long az0 = pack2(bz_, 0.f), az1 = pack2(0.f, 0.f);
        unsigned long long an0 = pack2(bn_, 0.f), an1 = pack2(0.f, 0.f);
#pragma unroll
        for (int k = 0; k < 16; k++) {
            ulonglong2 hv = hp[k];                  // broadcast LDS.128
            ar0 = fma2(wr[2 * k], hv.x, ar0);
            ar1 = fma2(wr[2 * k + 1], hv.y, ar1);
            az0 = fma2(wz[2 * k], hv.x, az0);
            az1 = fma2(wz[2 * k + 1], hv.y, az1);
            an0 = fma2(wn_[2 * k], hv.x, an0);
            an1 = fma2(wn_[2 * k + 1], hv.y, an1);
        }
        float2 pr0 = unpack2(ar0), pr1 = unpack2(ar1);
        float2 pz0 = unpack2(az0), pz1 = unpack2(az1);
        float2 pn0 = unpack2(an0), pn1 = unpack2(an1);
        float hr = (pr0.x + pr0.y) + (pr1.x + pr1.y);
        float hz = (pz0.x + pz0.y) + (pz1.x + pz1.y);
        float hn = (pn0.x + pn0.y) + (pn1.x + pn1.y);

        float r = sigmoidf_(xr0 + hr);
        float z = sigmoidf_(xz0 + hz);
        float n = tanhf_(xn0 + r * hn);
        hreg = fmaf(z, hreg - n, n);                // (1-z)*n + z*h
        hbuf[(s + 1) & 1][u] = hreg;

        if (s == 0)
            g_feat[b * 256 + (dir ? 192 : 0) + u] = hreg;
        if (s == T_ - 1)
            g_feat[b * 256 + (dir ? 64 : 128) + u] = hreg;

        xr0 = xr1; xz0 = xz1; xn0 = xn1;
        if (s + 2 < T_) {
            xr1 = p[0]; xz1 = p[64]; xn1 = p[128];
        }
        p += stp;
        __syncthreads();
    }
}

// ---------------------------------------------------------------------------
// Kernel 3: head MLP  feat[256] -> 32 (LeakyReLU) -> 1
//   one batch per block (grid 256), W1 via L2 (32KB, resident after block 0)
// ---------------------------------------------------------------------------
__global__ __launch_bounds__(256) void head_kernel(
    const float* __restrict__ W1, const float* __restrict__ b1,
    const float* __restrict__ W2, const float* __restrict__ b2,
    float* __restrict__ out) {
    __shared__ float fs[256];
    __shared__ float hs[32];
    const int b = blockIdx.x;
    const int tid = threadIdx.x;
    fs[tid] = g_feat[b * 256 + tid];
    __syncthreads();

    const int j = tid >> 3, p = tid & 7;
    const float* w = W1 + j * 256 + p * 32;
    const float* f = fs + p * 32;
    float acc = 0.f;
#pragma unroll
    for (int i = 0; i < 32; i++) acc = fmaf(f[i], w[i], acc);
    acc += __shfl_xor_sync(0xffffffffu, acc, 1);
    acc += __shfl_xor_sync(0xffffffffu, acc, 2);
    acc += __shfl_xor_sync(0xffffffffu, acc, 4);
    if (p == 0) {
        float hv = acc + b1[j];
        hv = (hv >= 0.f) ? hv : 0.01f * hv;
        hs[j] = hv * W2[j];
    }
    __syncthreads();
    if (tid < 32) {
        float v = hs[tid];
#pragma unroll
        for (int o = 16; o > 0; o >>= 1) v += __shfl_xor_sync(0xffffffffu, v, o);
        if (tid == 0) out[b] = v + b2[0];
    }
}

// ---------------------------------------------------------------------------
extern "C" void kernel_launch(void* const* d_in, const int* in_sizes, int n_in,
                              void* d_out, int out_size) {
    const float* x    = (const float*)d_in[0];
    const float* Wif  = (const float*)d_in[1];
    const float* Whhf = (const float*)d_in[2];
    const float* bif  = (const float*)d_in[3];
    const float* bhhf = (const float*)d_in[4];
    const float* Wib  = (const float*)d_in[5];
    const float* Whhb = (const float*)d_in[6];
    const float* bib  = (const float*)d_in[7];
    const float* bhhb = (const float*)d_in[8];
    const float* W1   = (const float*)d_in[9];
    const float* b1   = (const float*)d_in[10];
    const float* W2   = (const float*)d_in[11];
    const float* b2   = (const float*)d_in[12];
    float* out = (float*)d_out;

    cudaFuncSetAttribute(gemm_mma, cudaFuncAttributeMaxDynamicSharedMemorySize,
                         GSMEM);

    prep_kernel<<<(NCAT * KP + 255) / 256, 256>>>(Wif, Wib, bif, bib);
    dummyA_kernel<<<1, 32>>>();
    dummyB_kernel<<<1, 32>>>();

    dim3 ggrid(M_ / BM, NCAT / BN);
    gemm_mma<<<ggrid, 256, GSMEM>>>(x);     // 4th launch -> ncu capture

    scan_kernel<<<2 * B_, 64>>>(Whhf, Whhb, bhhf, bhhb);

    head_kernel<<<B_, 256>>>(W1, b1, W2, b2, out);
}

// round 14
// speedup vs baseline: 1.2893x; 1.0958x over previous
#include <cuda_runtime.h>
#include <cuda_fp16.h>
#include <cuda_bf16.h>
#include <cstdint>

// ---------------------------------------------------------------------------
// Problem constants
// ---------------------------------------------------------------------------
#define B_  256
#define T_  512
#define I_  300
#define H_  64
#define G3  192          // 3*H
#define NCAT 384         // 6*H
#define KP  320          // K padded (5 tiles of 64)
#define M_  (B_ * T_)    // 131072

#define BM 128
#define BN 128
#define BK 64
#define KTILES (KP / BK) // 5

// gemm smem stage layout (bytes): A1 | B1  (each 16KB, 128B rows)
#define STG   32768
#define OF_A1 0
#define OF_B1 16384
#define GSMEM (2 * STG)

// Scratch (static device memory; no allocation allowed)
__device__ float g_xp[(size_t)M_ * NCAT];         // ~201 MB
__device__ __half g_W1[NCAT * KP];                // W fp16, [n][k] K-major, padded
__device__ float g_bcat[NCAT];
__device__ float g_feat[B_ * 256];                // [b][ hf1 | hbF | hfF | hb1 ]

// ---------------------------------------------------------------------------
// MMA / ldmatrix / cp.async helpers (baseline PTX, legal on sm_103)
// ---------------------------------------------------------------------------
__device__ __forceinline__ uint32_t smem_u32(const void* p) {
    uint32_t a;
    asm("{ .reg .u64 t; cvta.to.shared.u64 t, %1; cvt.u32.u64 %0, t; }"
        : "=r"(a) : "l"(p));
    return a;
}
__device__ __forceinline__ void ldsm_x4(uint32_t addr, uint32_t& r0, uint32_t& r1,
                                        uint32_t& r2, uint32_t& r3) {
    asm volatile("ldmatrix.sync.aligned.m8n8.x4.shared.b16 {%0,%1,%2,%3}, [%4];"
                 : "=r"(r0), "=r"(r1), "=r"(r2), "=r"(r3) : "r"(addr));
}
__device__ __forceinline__ void mma16816h(float* d, const uint32_t* a,
                                          uint32_t b0, uint32_t b1) {
    asm volatile(
        "mma.sync.aligned.m16n8k16.row.col.f32.f16.f16.f32 "
        "{%0,%1,%2,%3}, {%4,%5,%6,%7}, {%8,%9}, {%0,%1,%2,%3};"
        : "+f"(d[0]), "+f"(d[1]), "+f"(d[2]), "+f"(d[3])
        : "r"(a[0]), "r"(a[1]), "r"(a[2]), "r"(a[3]), "r"(b0), "r"(b1));
}
__device__ __forceinline__ void cp_async16(uint32_t dst, const void* src) {
    asm volatile("cp.async.cg.shared.global [%0], [%1], 16;"
                 :: "r"(dst), "l"(src) : "memory");
}
__device__ __forceinline__ void cp_commit() {
    asm volatile("cp.async.commit_group;" ::: "memory");
}
__device__ __forceinline__ void cp_wait0() {
    asm volatile("cp.async.wait_group 0;" ::: "memory");
}

// swizzled byte offset within a [rows][64 fp16] tile (128B rows, SW128-style)
__device__ __forceinline__ uint32_t swzB(int r, int u) {
    return (uint32_t)(r * 128 + ((u ^ (r & 7)) << 4));
}

// ---------------------------------------------------------------------------
// f32x2 packed helpers (for scan)
// ---------------------------------------------------------------------------
__device__ __forceinline__ unsigned long long pack2(float lo, float hi) {
    unsigned long long r;
    asm("mov.b64 %0, {%1, %2};" : "=l"(r) : "f"(lo), "f"(hi));
    return r;
}
__device__ __forceinline__ unsigned long long fma2(unsigned long long a,
                                                   unsigned long long b,
                                                   unsigned long long c) {
    unsigned long long d;
    asm("fma.rn.f32x2 %0, %1, %2, %3;" : "=l"(d) : "l"(a), "l"(b), "l"(c));
    return d;
}
__device__ __forceinline__ float2 unpack2(unsigned long long v) {
    float lo, hi;
    asm("mov.b64 {%0, %1}, %2;" : "=f"(lo), "=f"(hi) : "l"(v));
    return make_float2(lo, hi);
}
__device__ __forceinline__ float sigmoidf_(float x) {
    return __fdividef(1.f, 1.f + __expf(-x));
}
__device__ __forceinline__ float tanhf_(float x) {
    return 1.f - __fdividef(2.f, 1.f + __expf(2.f * x));
}

// ---------------------------------------------------------------------------
// Dummy kernels: keep the profiler's 4th-launch capture on gemm_mma
// ---------------------------------------------------------------------------
__global__ void dummyA_kernel() {}
__global__ void dummyB_kernel() {}

// ---------------------------------------------------------------------------
// Kernel 0: build fp16 combined weight + fp32 bias
// ---------------------------------------------------------------------------
__global__ void prep_kernel(const float* __restrict__ Wif,
                            const float* __restrict__ Wib,
                            const float* __restrict__ bif,
                            const float* __restrict__ bib) {
    int i = blockIdx.x * blockDim.x + threadIdx.x;
    if (i < NCAT) g_bcat[i] = (i < G3) ? bif[i] : bib[i - G3];
    if (i < NCAT * KP) {
        int n = i / KP, k = i % KP;
        float v = 0.f;
        if (k < I_) v = (n < G3) ? Wif[n * I_ + k] : Wib[(n - G3) * I_ + k];
        g_W1[i] = __float2half_rn(v);
    }
}

// ---------------------------------------------------------------------------
// Kernel 1: HMMA fp16 single-pass GEMM — 512 threads / 16 warps (4M x 4N),
//   warp tile 32x32, BK=64, cp.async B, double-buffered smem,
//   ONE __syncthreads per K-tile.  xp = fp16(x) @ fp16(W)^T + bias
// ---------------------------------------------------------------------------
__global__ __launch_bounds__(512) void gemm_mma(const float* __restrict__ A) {
    extern __shared__ __align__(128) char smem[];

    const int tid = threadIdx.x;
    const int wid = tid >> 5;
    const int lid = tid & 31;
    const int m0 = blockIdx.x * BM;
    const int n0 = blockIdx.y * BN;

    const int wm = wid & 3;          // M quarter -> rows wm*32
    const int wn = wid >> 2;         // N quarter -> cols wn*32

    // A mapping: row = tid>>2 (0..127), 16 cols per thread
    const int ar = tid >> 2;
    const int acb = (tid & 3) * 16;
    const float* Arow = A + (size_t)(m0 + ar) * I_;

    // B mapping: row = tid>>2, two 16B chunks u = (tid&3)*2 + j
    const int br = tid >> 2;
    const int bu = (tid & 3) * 2;
    const __half* B1row = g_W1 + (size_t)(n0 + br) * KP;

    float4 va[4];

    // ---- preload stage 0 ----
    {
        char* st = smem;
#pragma unroll
        for (int j = 0; j < 2; j++)
            cp_async16(smem_u32(st + OF_B1) + swzB(br, bu + j),
                       B1row + (bu + j) * 8);
        cp_commit();
#pragma unroll
        for (int j = 0; j < 4; j++) {
            int c = acb + j * 4;
            va[j] = (c < I_) ? *(const float4*)(Arow + c)
                             : make_float4(0.f, 0.f, 0.f, 0.f);
        }
    }

    float acc[2][4][4];
#pragma unroll
    for (int i = 0; i < 2; i++)
#pragma unroll
        for (int j = 0; j < 4; j++)
#pragma unroll
            for (int q = 0; q < 4; q++) acc[i][j][q] = 0.f;

    for (int t = 0; t < KTILES; t++) {
        char* st = smem + (t & 1) * STG;
        // ---- convert + store A stage t (fp16, 2x STS.128) ----
#pragma unroll
        for (int m = 0; m < 2; m++) {
            float f[8] = {va[2 * m].x, va[2 * m].y, va[2 * m].z, va[2 * m].w,
                          va[2 * m + 1].x, va[2 * m + 1].y, va[2 * m + 1].z,
                          va[2 * m + 1].w};
            uint32_t hp[4];
#pragma unroll
            for (int q = 0; q < 4; q++) {
                __half2 hh = __halves2half2(__float2half_rn(f[2 * q]),
                                            __float2half_rn(f[2 * q + 1]));
                hp[q] = *(uint32_t*)&hh;
            }
            uint32_t off = swzB(ar, (acb >> 3) + m);
            *(uint4*)(st + OF_A1 + off) = make_uint4(hp[0], hp[1], hp[2], hp[3]);
        }

        cp_wait0();                    // B stage t landed
        __syncthreads();               // the ONLY barrier per tile

        // ---- kick off stage t+1 (B via cp.async, A via registers) ----
        if (t + 1 < KTILES) {
            char* sn = smem + ((t + 1) & 1) * STG;
            const int k0 = (t + 1) * BK;
#pragma unroll
            for (int j = 0; j < 2; j++)
                cp_async16(smem_u32(sn + OF_B1) + swzB(br, bu + j),
                           B1row + k0 + (bu + j) * 8);
            cp_commit();
#pragma unroll
            for (int j = 0; j < 4; j++) {
                int c = k0 + acb + j * 4;
                va[j] = (c < I_) ? *(const float4*)(Arow + c)
                                 : make_float4(0.f, 0.f, 0.f, 0.f);
            }
        }

        // ---- compute stage t: 4 k16 steps ----
        const uint32_t a1B = smem_u32(st + OF_A1);
        const uint32_t b1B = smem_u32(st + OF_B1);
#pragma unroll
        for (int s = 0; s < 4; s++) {
            uint32_t af1[2][4], bf1[2][4];
            const int rA = (lid & 15);
            const int uu = s * 2 + (lid >> 4);
#pragma unroll
            for (int i = 0; i < 2; i++) {
                int r = wm * 32 + i * 16 + rA;
                uint32_t o = swzB(r, uu);
                ldsm_x4(a1B + o, af1[i][0], af1[i][1], af1[i][2], af1[i][3]);
            }
#pragma unroll
            for (int j2 = 0; j2 < 2; j2++) {
                int r = wn * 32 + j2 * 16 + rA;
                uint32_t o = swzB(r, uu);
                ldsm_x4(b1B + o, bf1[j2][0], bf1[j2][1], bf1[j2][2], bf1[j2][3]);
            }
#pragma unroll
            for (int i = 0; i < 2; i++) {
#pragma unroll
                for (int j2 = 0; j2 < 2; j2++) {
#pragma unroll
                    for (int g = 0; g < 2; g++) {
                        int j = j2 * 2 + g;
                        mma16816h(acc[i][j], af1[i], bf1[j2][g], bf1[j2][g + 2]);
                    }
                }
            }
        }
    }

    const int erow = lid >> 2;
    const int ecol = (lid & 3) * 2;
#pragma unroll
    for (int i = 0; i < 2; i++) {
        int grow = m0 + wm * 32 + i * 16 + erow;
        float* out0 = g_xp + (size_t)grow * NCAT;
        float* out1 = g_xp + (size_t)(grow + 8) * NCAT;
#pragma unroll
        for (int j = 0; j < 4; j++) {
            int gcol = n0 + wn * 32 + j * 8 + ecol;
            float2 bi = *(const float2*)(g_bcat + gcol);
            *(float2*)(out0 + gcol) =
                make_float2(acc[i][j][0] + bi.x, acc[i][j][1] + bi.y);
            *(float2*)(out1 + gcol) =
                make_float2(acc[i][j][2] + bi.x, acc[i][j][3] + bi.y);
        }
    }
}

// ---------------------------------------------------------------------------
// Kernel 2: bidirectional GRU scan — R8-exact (measured best: 331us).
//   Grid 512 = (b, dir); block 64 threads, thread owns unit u with all three
//   W_hh rows in registers; ping-pong h in smem; ONE barrier per step.
// ---------------------------------------------------------------------------
__global__ __launch_bounds__(64) void scan_kernel(
    const float* __restrict__ Whhf, const float* __restrict__ Whhb,
    const float* __restrict__ bhhf, const float* __restrict__ bhhb) {
    __shared__ __align__(16) float hbuf[2][H_];      // [parity][unit]

    const int b = blockIdx.x >> 1;
    const int dir = blockIdx.x & 1;
    const int u = threadIdx.x;

    const float* Whh = dir ? Whhb : Whhf;
    const float* bhh = dir ? bhhb : bhhf;

    unsigned long long wr[32], wz[32], wn_[32];
    {
        const float2* r0 = (const float2*)(Whh + (size_t)u * H_);
        const float2* r1 = (const float2*)(Whh + (size_t)(64 + u) * H_);
        const float2* r2 = (const float2*)(Whh + (size_t)(128 + u) * H_);
#pragma unroll
        for (int k = 0; k < 32; k++) {
            float2 a = r0[k], c = r1[k], d = r2[k];
            wr[k] = pack2(a.x, a.y);
            wz[k] = pack2(c.x, c.y);
            wn_[k] = pack2(d.x, d.y);
        }
    }
    const float br_ = bhh[u];
    const float bz_ = bhh[64 + u];
    const float bn_ = bhh[128 + u];

    hbuf[0][u] = 0.f;
    float hreg = 0.f;

    const int stp = dir ? -NCAT : NCAT;
    const float* p = g_xp + (size_t)b * (T_ * NCAT) +
                     (dir ? (size_t)(T_ - 1) * NCAT : 0) + dir * G3 + u;
    float xr0 = p[0], xz0 = p[64], xn0 = p[128];
    p += stp;
    float xr1 = p[0], xz1 = p[64], xn1 = p[128];
    p += stp;
    __syncthreads();

    for (int s = 0; s < T_; s++) {
        const ulonglong2* hp = (const ulonglong2*)hbuf[s & 1];
        unsigned long long ar0 = pack2(br_, 0.f), ar1 = pack2(0.f, 0.f);
        unsigned long long az0 = pack2(bz_, 0.f), az1 = pack2(0.f, 0.f);
        unsigned long long an0 = pack2(bn_, 0.f), an1 = pack2(0.f, 0.f);
#pragma unroll
        for (int k = 0; k < 16; k++) {
            ulonglong2 hv = hp[k];                  // broadcast LDS.128
            ar0 = fma2(wr[2 * k], hv.x, ar0);
            ar1 = fma2(wr[2 * k + 1], hv.y, ar1);
            az0 = fma2(wz[2 * k], hv.x, az0);
            az1 = fma2(wz[2 * k + 1], hv.y, az1);
            an0 = fma2(wn_[2 * k], hv.x, an0);
            an1 = fma2(wn_[2 * k + 1], hv.y, an1);
        }
        float2 pr0 = unpack2(ar0), pr1 = unpack2(ar1);
        float2 pz0 = unpack2(az0), pz1 = unpack2(az1);
        float2 pn0 = unpack2(an0), pn1 = unpack2(an1);
        float hr = (pr0.x + pr0.y) + (pr1.x + pr1.y);
        float hz = (pz0.x + pz0.y) + (pz1.x + pz1.y);
        float hn = (pn0.x + pn0.y) + (pn1.x + pn1.y);

        float r = sigmoidf_(xr0 + hr);
        float z = sigmoidf_(xz0 + hz);
        float n = tanhf_(xn0 + r * hn);
        hreg = fmaf(z, hreg - n, n);                // (1-z)*n + z*h
        hbuf[(s + 1) & 1][u] = hreg;

        if (s == 0)
            g_feat[b * 256 + (dir ? 192 : 0) + u] = hreg;
        if (s == T_ - 1)
            g_feat[b * 256 + (dir ? 64 : 128) + u] = hreg;

        xr0 = xr1; xz0 = xz1; xn0 = xn1;
        if (s + 2 < T_) {
            xr1 = p[0]; xz1 = p[64]; xn1 = p[128];
        }
        p += stp;
        __syncthreads();
    }
}

// ---------------------------------------------------------------------------
// Kernel 3: head MLP  feat[256] -> 32 (LeakyReLU) -> 1
//   one batch per block (grid 256)
// ---------------------------------------------------------------------------
__global__ __launch_bounds__(256) void head_kernel(
    const float* __restrict__ W1, const float* __restrict__ b1,
    const float* __restrict__ W2, const float* __restrict__ b2,
    float* __restrict__ out) {
    __shared__ float fs[256];
    __shared__ float hs[32];
    const int b = blockIdx.x;
    const int tid = threadIdx.x;
    fs[tid] = g_feat[b * 256 + tid];
    __syncthreads();

    const int j = tid >> 3, p = tid & 7;
    const float* w = W1 + j * 256 + p * 32;
    const float* f = fs + p * 32;
    float acc = 0.f;
#pragma unroll
    for (int i = 0; i < 32; i++) acc = fmaf(f[i], w[i], acc);
    acc += __shfl_xor_sync(0xffffffffu, acc, 1);
    acc += __shfl_xor_sync(0xffffffffu, acc, 2);
    acc += __shfl_xor_sync(0xffffffffu, acc, 4);
    if (p == 0) {
        float hv = acc + b1[j];
        hv = (hv >= 0.f) ? hv : 0.01f * hv;
        hs[j] = hv * W2[j];
    }
    __syncthreads();
    if (tid < 32) {
        float v = hs[tid];
#pragma unroll
        for (int o = 16; o > 0; o >>= 1) v += __shfl_xor_sync(0xffffffffu, v, o);
        if (tid == 0) out[b] = v + b2[0];
    }
}

// ---------------------------------------------------------------------------
extern "C" void kernel_launch(void* const* d_in, const int* in_sizes, int n_in,
                              void* d_out, int out_size) {
    const float* x    = (const float*)d_in[0];
    const float* Wif  = (const float*)d_in[1];
    const float* Whhf = (const float*)d_in[2];
    const float* bif  = (const float*)d_in[3];
    const float* bhhf = (const float*)d_in[4];
    const float* Wib  = (const float*)d_in[5];
    const float* Whhb = (const float*)d_in[6];
    const float* bib  = (const float*)d_in[7];
    const float* bhhb = (const float*)d_in[8];
    const float* W1   = (const float*)d_in[9];
    const float* b1   = (const float*)d_in[10];
    const float* W2   = (const float*)d_in[11];
    const float* b2   = (const float*)d_in[12];
    float* out = (float*)d_out;

    cudaFuncSetAttribute(gemm_mma, cudaFuncAttributeMaxDynamicSharedMemorySize,
                         GSMEM);

    prep_kernel<<<(NCAT * KP + 255) / 256, 256>>>(Wif, Wib, bif, bib);
    dummyA_kernel<<<1, 32>>>();
    dummyB_kernel<<<1, 32>>>();

    dim3 ggrid(M_ / BM, NCAT / BN);
    gemm_mma<<<ggrid, 512, GSMEM>>>(x);     // 4th launch -> ncu capture

    scan_kernel<<<2 * B_, 64>>>(Whhf, Whhb, bhhf, bhhb);

    head_kernel<<<B_, 256>>>(W1, b1, W2, b2, out);
}

// round 15
// speedup vs baseline: 1.3907x; 1.0786x over previous
#include <cuda_runtime.h>
#include <cuda_fp16.h>
#include <cuda_bf16.h>
#include <cstdint>

// ---------------------------------------------------------------------------
// Problem constants
// ---------------------------------------------------------------------------
#define B_  256
#define T_  512
#define I_  300
#define H_  64
#define G3  192          // 3*H
#define NCAT 384         // 6*H
#define KP  320          // K padded (5 tiles of 64)
#define M_  (B_ * T_)    // 131072

#define BM 128
#define BN 128
#define BK 64
#define KTILES (KP / BK) // 5
#define NBLK (NCAT / BN) // 3
#define NITER (NBLK * KTILES) // 15

// gemm smem layout (bytes): sA[5] slabs (16KB each) | sB double (2 x 16KB)
#define SLAB  16384
#define OF_B  (5 * SLAB)          // 81920
#define GSMEM (7 * SLAB)          // 114688

// Scratch (static device memory; no allocation allowed)
__device__ float g_xp[(size_t)M_ * NCAT];         // ~201 MB
__device__ __half g_W1[NCAT * KP];                // W fp16, [n][k] K-major, padded
__device__ float g_bcat[NCAT];
__device__ float g_feat[B_ * 256];                // [b][ hf1 | hbF | hfF | hb1 ]

// ---------------------------------------------------------------------------
// MMA / ldmatrix / cp.async helpers (baseline PTX, legal on sm_103)
// ---------------------------------------------------------------------------
__device__ __forceinline__ uint32_t smem_u32(const void* p) {
    uint32_t a;
    asm("{ .reg .u64 t; cvta.to.shared.u64 t, %1; cvt.u32.u64 %0, t; }"
        : "=r"(a) : "l"(p));
    return a;
}
__device__ __forceinline__ void ldsm_x4(uint32_t addr, uint32_t& r0, uint32_t& r1,
                                        uint32_t& r2, uint32_t& r3) {
    asm volatile("ldmatrix.sync.aligned.m8n8.x4.shared.b16 {%0,%1,%2,%3}, [%4];"
                 : "=r"(r0), "=r"(r1), "=r"(r2), "=r"(r3) : "r"(addr));
}
__device__ __forceinline__ void mma16816h(float* d, const uint32_t* a,
                                          uint32_t b0, uint32_t b1) {
    asm volatile(
        "mma.sync.aligned.m16n8k16.row.col.f32.f16.f16.f32 "
        "{%0,%1,%2,%3}, {%4,%5,%6,%7}, {%8,%9}, {%0,%1,%2,%3};"
        : "+f"(d[0]), "+f"(d[1]), "+f"(d[2]), "+f"(d[3])
        : "r"(a[0]), "r"(a[1]), "r"(a[2]), "r"(a[3]), "r"(b0), "r"(b1));
}
__device__ __forceinline__ void cp_async16(uint32_t dst, const void* src) {
    asm volatile("cp.async.cg.shared.global [%0], [%1], 16;"
                 :: "r"(dst), "l"(src) : "memory");
}
__device__ __forceinline__ void cp_commit() {
    asm volatile("cp.async.commit_group;" ::: "memory");
}
__device__ __forceinline__ void cp_wait0() {
    asm volatile("cp.async.wait_group 0;" ::: "memory");
}

// swizzled byte offset within a [rows][64 fp16] tile (128B rows, SW128-style)
__device__ __forceinline__ uint32_t swzB(int r, int u) {
    return (uint32_t)(r * 128 + ((u ^ (r & 7)) << 4));
}

// ---------------------------------------------------------------------------
// f32x2 packed helpers (for scan)
// ---------------------------------------------------------------------------
__device__ __forceinline__ unsigned long long pack2(float lo, float hi) {
    unsigned long long r;
    asm("mov.b64 %0, {%1, %2};" : "=l"(r) : "f"(lo), "f"(hi));
    return r;
}
__device__ __forceinline__ unsigned long long fma2(unsigned long long a,
                                                   unsigned long long b,
                                                   unsigned long long c) {
    unsigned long long d;
    asm("fma.rn.f32x2 %0, %1, %2, %3;" : "=l"(d) : "l"(a), "l"(b), "l"(c));
    return d;
}
__device__ __forceinline__ float2 unpack2(unsigned long long v) {
    float lo, hi;
    asm("mov.b64 {%0, %1}, %2;" : "=f"(lo), "=f"(hi) : "l"(v));
    return make_float2(lo, hi);
}
__device__ __forceinline__ float sigmoidf_(float x) {
    return __fdividef(1.f, 1.f + __expf(-x));
}
__device__ __forceinline__ float tanhf_(float x) {
    return 1.f - __fdividef(2.f, 1.f + __expf(2.f * x));
}

// ---------------------------------------------------------------------------
// Dummy kernels: keep the profiler's 4th-launch capture on gemm_mma
// ---------------------------------------------------------------------------
__global__ void dummyA_kernel() {}
__global__ void dummyB_kernel() {}

// ---------------------------------------------------------------------------
// Kernel 0: build fp16 combined weight + fp32 bias
// ---------------------------------------------------------------------------
__global__ void prep_kernel(const float* __restrict__ Wif,
                            const float* __restrict__ Wib,
                            const float* __restrict__ bif,
                            const float* __restrict__ bib) {
    int i = blockIdx.x * blockDim.x + threadIdx.x;
    if (i < NCAT) g_bcat[i] = (i < G3) ? bif[i] : bib[i - G3];
    if (i < NCAT * KP) {
        int n = i / KP, k = i % KP;
        float v = 0.f;
        if (k < I_) v = (n < G3) ? Wif[n * I_ + k] : Wib[(n - G3) * I_ + k];
        g_W1[i] = __float2half_rn(v);
    }
}

// ---------------------------------------------------------------------------
// Kernel 1: HMMA fp16 GEMM with smem-resident A across all 3 N-blocks.
//   512 threads / 16 warps (4M x 4N), warp tile 32x32, BK=64.
//   A loaded+converted ONCE into 5 persistent slabs; B double-buffered
//   via cp.async; flattened (n,t) loop, ONE __syncthreads per iteration.
//   xp = fp16(x) @ fp16(W)^T + bias
// ---------------------------------------------------------------------------
__global__ __launch_bounds__(512) void gemm_mma(const float* __restrict__ A) {
    extern __shared__ __align__(128) char smem[];

    const int tid = threadIdx.x;
    const int wid = tid >> 5;
    const int lid = tid & 31;
    const int m0 = blockIdx.x * BM;

    const int wm = wid & 3;          // M quarter -> rows wm*32
    const int wn = wid >> 2;         // N quarter -> cols wn*32

    // A mapping: row = tid>>2 (0..127), 16 cols per thread
    const int ar = tid >> 2;
    const int acb = (tid & 3) * 16;
    const float* Arow = A + (size_t)(m0 + ar) * I_;

    // B mapping: row = tid>>2, two 16B chunks u = (tid&3)*2 + j
    const int br = tid >> 2;
    const int bu = (tid & 3) * 2;
    const __half* Bbase = g_W1 + (size_t)br * KP;   // + n0*KP per n-block

    float4 va[4];

    // ---- preload: B(n=0,t=0) and A regs for tile 0 ----
    {
#pragma unroll
        for (int j = 0; j < 2; j++)
            cp_async16(smem_u32(smem + OF_B) + swzB(br, bu + j),
                       Bbase + (bu + j) * 8);
        cp_commit();
#pragma unroll
        for (int j = 0; j < 4; j++) {
            int c = acb + j * 4;
            va[j] = (c < I_) ? *(const float4*)(Arow + c)
                             : make_float4(0.f, 0.f, 0.f, 0.f);
        }
    }

    float acc[2][4][4];
#pragma unroll
    for (int i = 0; i < 2; i++)
#pragma unroll
        for (int j = 0; j < 4; j++)
#pragma unroll
            for (int q = 0; q < 4; q++) acc[i][j][q] = 0.f;

    const int rA = lid & 15;
    const int uhalf = lid >> 4;
    const int erow = lid >> 2;
    const int ecol = (lid & 3) * 2;

    for (int it = 0; it < NITER; it++) {
        const int t = it % KTILES;
        char* sAt = smem + t * SLAB;

        // ---- first N-pass: convert + store A tile t ----
        if (it < KTILES) {
#pragma unroll
            for (int m = 0; m < 2; m++) {
                float f[8] = {va[2 * m].x, va[2 * m].y, va[2 * m].z,
                              va[2 * m].w, va[2 * m + 1].x, va[2 * m + 1].y,
                              va[2 * m + 1].z, va[2 * m + 1].w};
                uint32_t hp[4];
#pragma unroll
                for (int q = 0; q < 4; q++) {
                    __half2 hh = __halves2half2(__float2half_rn(f[2 * q]),
                                                __float2half_rn(f[2 * q + 1]));
                    hp[q] = *(uint32_t*)&hh;
                }
                uint32_t off = swzB(ar, (acb >> 3) + m);
                *(uint4*)(sAt + off) = make_uint4(hp[0], hp[1], hp[2], hp[3]);
            }
        }

        cp_wait0();                    // B(it) landed
        __syncthreads();               // also: all compute of it-1 done

        // ---- kick off iteration it+1 ----
        if (it + 1 < NITER) {
            const int tn = (it + 1) % KTILES;
            const int nn = (it + 1) / KTILES;
            char* sBn = smem + OF_B + ((it + 1) & 1) * SLAB;
            const __half* Bn = Bbase + (size_t)(nn * BN) * KP + tn * BK;
#pragma unroll
            for (int j = 0; j < 2; j++)
                cp_async16(smem_u32(sBn) + swzB(br, bu + j), Bn + (bu + j) * 8);
            cp_commit();
            if (it + 1 < KTILES) {     // A regs for next conversion
                const int k0 = (it + 1) * BK;
#pragma unroll
                for (int j = 0; j < 4; j++) {
                    int c = k0 + acb + j * 4;
                    va[j] = (c < I_) ? *(const float4*)(Arow + c)
                                     : make_float4(0.f, 0.f, 0.f, 0.f);
                }
            }
        }

        // ---- compute iteration it: 4 k16 steps ----
        const uint32_t a1B = smem_u32(sAt);
        const uint32_t b1B = smem_u32(smem + OF_B + (it & 1) * SLAB);
#pragma unroll
        for (int s = 0; s < 4; s++) {
            uint32_t af1[2][4], bf1[2][4];
            const int uu = s * 2 + uhalf;
#pragma unroll
            for (int i = 0; i < 2; i++) {
                uint32_t o = swzB(wm * 32 + i * 16 + rA, uu);
                ldsm_x4(a1B + o, af1[i][0], af1[i][1], af1[i][2], af1[i][3]);
            }
#pragma unroll
            for (int j2 = 0; j2 < 2; j2++) {
                uint32_t o = swzB(wn * 32 + j2 * 16 + rA, uu);
                ldsm_x4(b1B + o, bf1[j2][0], bf1[j2][1], bf1[j2][2], bf1[j2][3]);
            }
#pragma unroll
            for (int i = 0; i < 2; i++) {
#pragma unroll
                for (int j2 = 0; j2 < 2; j2++) {
#pragma unroll
                    for (int g = 0; g < 2; g++) {
                        int j = j2 * 2 + g;
                        mma16816h(acc[i][j], af1[i], bf1[j2][g], bf1[j2][g + 2]);
                    }
                }
            }
        }

        // ---- end of an N-pass: epilogue + reset acc ----
        if (t == KTILES - 1) {
            const int n0 = (it / KTILES) * BN;
#pragma unroll
            for (int i = 0; i < 2; i++) {
                int grow = m0 + wm * 32 + i * 16 + erow;
                float* out0 = g_xp + (size_t)grow * NCAT;
                float* out1 = g_xp + (size_t)(grow + 8) * NCAT;
#pragma unroll
                for (int j = 0; j < 4; j++) {
                    int gcol = n0 + wn * 32 + j * 8 + ecol;
                    float2 bi = *(const float2*)(g_bcat + gcol);
                    *(float2*)(out0 + gcol) =
                        make_float2(acc[i][j][0] + bi.x, acc[i][j][1] + bi.y);
                    *(float2*)(out1 + gcol) =
                        make_float2(acc[i][j][2] + bi.x, acc[i][j][3] + bi.y);
                    acc[i][j][0] = 0.f; acc[i][j][1] = 0.f;
                    acc[i][j][2] = 0.f; acc[i][j][3] = 0.f;
                }
            }
        }
    }
}

// ---------------------------------------------------------------------------
// Kernel 2: bidirectional GRU scan — R8-exact (measured best: 331us).
//   Grid 512 = (b, dir); block 64 threads, thread owns unit u with all three
//   W_hh rows in registers; ping-pong h in smem; ONE barrier per step.
// ---------------------------------------------------------------------------
__global__ __launch_bounds__(64) void scan_kernel(
    const float* __restrict__ Whhf, const float* __restrict__ Whhb,
    const float* __restrict__ bhhf, const float* __restrict__ bhhb) {
    __shared__ __align__(16) float hbuf[2][H_];      // [parity][unit]

    const int b = blockIdx.x >> 1;
    const int dir = blockIdx.x & 1;
    const int u = threadIdx.x;

    const float* Whh = dir ? Whhb : Whhf;
    const float* bhh = dir ? bhhb : bhhf;

    unsigned long long wr[32], wz[32], wn_[32];
    {
        const float2* r0 = (const float2*)(Whh + (size_t)u * H_);
        const float2* r1 = (const float2*)(Whh + (size_t)(64 + u) * H_);
        const float2* r2 = (const float2*)(Whh + (size_t)(128 + u) * H_);
#pragma unroll
        for (int k = 0; k < 32; k++) {
            float2 a = r0[k], c = r1[k], d = r2[k];
            wr[k] = pack2(a.x, a.y);
            wz[k] = pack2(c.x, c.y);
            wn_[k] = pack2(d.x, d.y);
        }
    }
    const float br_ = bhh[u];
    const float bz_ = bhh[64 + u];
    const float bn_ = bhh[128 + u];

    hbuf[0][u] = 0.f;
    float hreg = 0.f;

    const int stp = dir ? -NCAT : NCAT;
    const float* p = g_xp + (size_t)b * (T_ * NCAT) +
                     (dir ? (size_t)(T_ - 1) * NCAT : 0) + dir * G3 + u;
    float xr0 = p[0], xz0 = p[64], xn0 = p[128];
    p += stp;
    float xr1 = p[0], xz1 = p[64], xn1 = p[128];
    p += stp;
    __syncthreads();

    for (int s = 0; s < T_; s++) {
        const ulonglong2* hp = (const ulonglong2*)hbuf[s & 1];
        unsigned long long ar0 = pack2(br_, 0.f), ar1 = pack2(0.f, 0.f);
        unsigned long long az0 = pack2(bz_, 0.f), az1 = pack2(0.f, 0.f);
        unsigned long long an0 = pack2(bn_, 0.f), an1 = pack2(0.f, 0.f);
#pragma unroll
        for (int k = 0; k < 16; k++) {
            ulonglong2 hv = hp[k];                  // broadcast LDS.128
            ar0 = fma2(wr[2 * k], hv.x, ar0);
            ar1 = fma2(wr[2 * k + 1], hv.y, ar1);
            az0 = fma2(wz[2 * k], hv.x, az0);
            az1 = fma2(wz[2 * k + 1], hv.y, az1);
            an0 = fma2(wn_[2 * k], hv.x, an0);
            an1 = fma2(wn_[2 * k + 1], hv.y, an1);
        }
        float2 pr0 = unpack2(ar0), pr1 = unpack2(ar1);
        float2 pz0 = unpack2(az0), pz1 = unpack2(az1);
        float2 pn0 = unpack2(an0), pn1 = unpack2(an1);
        float hr = (pr0.x + pr0.y) + (pr1.x + pr1.y);
        float hz = (pz0.x + pz0.y) + (pz1.x + pz1.y);
        float hn = (pn0.x + pn0.y) + (pn1.x + pn1.y);

        float r = sigmoidf_(xr0 + hr);
        float z = sigmoidf_(xz0 + hz);
        float n = tanhf_(xn0 + r * hn);
        hreg = fmaf(z, hreg - n, n);                // (1-z)*n + z*h
        hbuf[(s + 1) & 1][u] = hreg;

        if (s == 0)
            g_feat[b * 256 + (dir ? 192 : 0) + u] = hreg;
        if (s == T_ - 1)
            g_feat[b * 256 + (dir ? 64 : 128) + u] = hreg;

        xr0 = xr1; xz0 = xz1; xn0 = xn1;
        if (s + 2 < T_) {
            xr1 = p[0]; xz1 = p[64]; xn1 = p[128];
        }
        p += stp;
        __syncthreads();
    }
}

// ---------------------------------------------------------------------------
// Kernel 3: head MLP  feat[256] -> 32 (LeakyReLU) -> 1
//   one batch per block (grid 256)
// ---------------------------------------------------------------------------
__global__ __launch_bounds__(256) void head_kernel(
    const float* __restrict__ W1, const float* __restrict__ b1,
    const float* __restrict__ W2, const float* __restrict__ b2,
    float* __restrict__ out) {
    __shared__ float fs[256];
    __shared__ float hs[32];
    const int b = blockIdx.x;
    const int tid = threadIdx.x;
    fs[tid] = g_feat[b * 256 + tid];
    __syncthreads();

    const int j = tid >> 3, p = tid & 7;
    const float* w = W1 + j * 256 + p * 32;
    const float* f = fs + p * 32;
    float acc = 0.f;
#pragma unroll
    for (int i = 0; i < 32; i++) acc = fmaf(f[i], w[i], acc);
    acc += __shfl_xor_sync(0xffffffffu, acc, 1);
    acc += __shfl_xor_sync(0xffffffffu, acc, 2);
    acc += __shfl_xor_sync(0xffffffffu, acc, 4);
    if (p == 0) {
        float hv = acc + b1[j];
        hv = (hv >= 0.f) ? hv : 0.01f * hv;
        hs[j] = hv * W2[j];
    }
    __syncthreads();
    if (tid < 32) {
        float v = hs[tid];
#pragma unroll
        for (int o = 16; o > 0; o >>= 1) v += __shfl_xor_sync(0xffffffffu, v, o);
        if (tid == 0) out[b] = v + b2[0];
    }
}

// ---------------------------------------------------------------------------
extern "C" void kernel_launch(void* const* d_in, const int* in_sizes, int n_in,
                              void* d_out, int out_size) {
    const float* x    = (const float*)d_in[0];
    const float* Wif  = (const float*)d_in[1];
    const float* Whhf = (const float*)d_in[2];
    const float* bif  = (const float*)d_in[3];
    const float* bhhf = (const float*)d_in[4];
    const float* Wib  = (const float*)d_in[5];
    const float* Whhb = (const float*)d_in[6];
    const float* bib  = (const float*)d_in[7];
    const float* bhhb = (const float*)d_in[8];
    const float* W1   = (const float*)d_in[9];
    const float* b1   = (const float*)d_in[10];
    const float* W2   = (const float*)d_in[11];
    const float* b2   = (const float*)d_in[12];
    float* out = (float*)d_out;

    cudaFuncSetAttribute(gemm_mma, cudaFuncAttributeMaxDynamicSharedMemorySize,
                         GSMEM);

    prep_kernel<<<(NCAT * KP + 255) / 256, 256>>>(Wif, Wib, bif, bib);
    dummyA_kernel<<<1, 32>>>();
    dummyB_kernel<<<1, 32>>>();

    gemm_mma<<<M_ / BM, 512, GSMEM>>>(x);   // 4th launch -> ncu capture

    scan_kernel<<<2 * B_, 64>>>(Whhf, Whhb, bhhf, bhhb);

    head_kernel<<<B_, 256>>>(W1, b1, W2, b2, out);
}